// round 15
// baseline (speedup 1.0000x reference)
#include <cuda_runtime.h>
#include <cstdint>

#define T_STEPS 512
#define BATCH   64
#define IN_DIM  256
#define HID     512
#define OUT_DIM 256
#define G4      2048
#define NCTA    128

#define SW2_STRIDE  1032
#define SW2_FLOATS  (16 * SW2_STRIDE)      // 16512
#define SRED_STRIDE 36
#define SRED_FLOATS (256 * SRED_STRIDE)    // 9216
#define RSMEM_BYTES ((SW2_FLOATS + SRED_FLOATS) * 4)   // 102912

#define XG_SMEM  131072   // sAhi 64K + sAlo 64K (bytes); B read direct from gmem
#define GO_SMEM  196608   // sBhi 64K + sBlo 64K + sAhi 32K + sAlo 32K

#define OFF_H ((size_t)T_STEPS * BATCH * OUT_DIM)
#define OFF_C (OFF_H + (size_t)BATCH * HID)

typedef unsigned long long ull;

__device__ float    g_xg[(size_t)T_STEPS * G4 * BATCH];   // [t][g][b]
__device__ float    g_hs[(size_t)T_STEPS * HID * BATCH];  // [t][k][b]
__device__ float    g_bsum[G4];
__device__ unsigned g_bar;
__device__ unsigned g_flag;

// pre-split tf32 operands in fragment-permuted layouts
__device__ uint32_t g_Whi [32u * 16384u];        // [tile32][ks32][mf4][lane32][4]
__device__ uint32_t g_Wlo [32u * 16384u];
__device__ uint32_t g_Xhi [(size_t)T_STEPS * 16384u];   // [t][ks32][nf8][lane32][2]
__device__ uint32_t g_Xlo [(size_t)T_STEPS * 16384u];
__device__ uint32_t g_WOhi[2u * 65536u];         // [tile2][ks64][nf16][lane32][2]
__device__ uint32_t g_WOlo[2u * 65536u];
__device__ uint32_t g_Hhi [(size_t)T_STEPS * 32768u];   // [t][ks64][mf4][lane32][4]
__device__ uint32_t g_Hlo [(size_t)T_STEPS * 32768u];

// ---------------- helpers ----------------
__device__ __forceinline__ void ffma2(ull& d, ull a, ull b) {
    asm("fma.rn.f32x2 %0, %1, %2, %0;" : "+l"(d) : "l"(a), "l"(b));
}
__device__ __forceinline__ float2 unpack2(ull v) {
    float2 r; asm("mov.b64 {%0, %1}, %2;" : "=f"(r.x), "=f"(r.y) : "l"(v)); return r;
}
__device__ __forceinline__ float sigf(float x) {
    return __fdividef(1.f, 1.f + __expf(-x));
}
__device__ __forceinline__ float tanhfast(float x) {
    float e = __expf(-2.f * fabsf(x));
    float r = __fdividef(1.f - e, 1.f + e);
    return copysignf(r, x);
}
__device__ __forceinline__ void mma8(float* d, const uint32_t* a, const uint32_t* b) {
    asm volatile(
        "mma.sync.aligned.m16n8k8.row.col.f32.tf32.tf32.f32 "
        "{%0,%1,%2,%3}, {%4,%5,%6,%7}, {%8,%9}, {%0,%1,%2,%3};"
        : "+f"(d[0]), "+f"(d[1]), "+f"(d[2]), "+f"(d[3])
        : "r"(a[0]), "r"(a[1]), "r"(a[2]), "r"(a[3]), "r"(b[0]), "r"(b[1]));
}
__device__ __forceinline__ void cpa16(uint32_t d, const void* s) {
    asm volatile("cp.async.cg.shared.global [%0], [%1], 16;" :: "r"(d), "l"(s) : "memory");
}
#define CP_COMMIT()  asm volatile("cp.async.commit_group;" ::: "memory")
#define CP_WAIT0()   asm volatile("cp.async.wait_group 0;" ::: "memory")

__global__ void reset_kernel(const float* __restrict__ b_ih,
                             const float* __restrict__ b_hh) {
    int idx = blockIdx.x * blockDim.x + threadIdx.x;
    if (idx == 0) { g_bar = 0u; g_flag = 0u; }
    if (idx < G4) g_bsum[idx] = b_ih[idx] + b_hh[idx];
}

// ---------------- prep (gather style: coalesced writes, sector-aligned reads)
// masked tf32 split: hi = x & 0xFFFFE000 (cannot be folded away), lo = x - hi.
__global__ void prep_W(const float* __restrict__ W) {
    int idx = blockIdx.x * blockDim.x + threadIdx.x;    // 524288
    int r    = idx & 3;
    int lane = (idx >> 2) & 31;
    int mf   = (idx >> 7) & 3;
    int ks   = (idx >> 9) & 31;
    int tile = idx >> 14;
    int m = tile * 64 + mf * 16 + (r & 1) * 8 + (lane >> 2);
    int k = ks * 8 + ((r >> 1) & 1) * 4 + (lane & 3);
    float x = __ldg(W + (size_t)m * IN_DIM + k);
    uint32_t h = __float_as_uint(x) & 0xFFFFE000u;
    g_Whi[idx] = h;
    g_Wlo[idx] = __float_as_uint(x - __uint_as_float(h));
}

__global__ void prep_X(const float* __restrict__ inp) {
    int idx = blockIdx.x * blockDim.x + threadIdx.x;    // 8388608
    int r    = idx & 1;
    int lane = (idx >> 1) & 31;
    int nf   = (idx >> 6) & 7;
    int ks   = (idx >> 9) & 31;
    int t    = idx >> 14;
    int b = nf * 8 + (lane >> 2);
    int k = ks * 8 + r * 4 + (lane & 3);
    float x = __ldg(inp + ((size_t)t * BATCH + b) * IN_DIM + k);
    uint32_t h = __float_as_uint(x) & 0xFFFFE000u;
    g_Xhi[idx] = h;
    g_Xlo[idx] = __float_as_uint(x - __uint_as_float(h));
}

__global__ void prep_WO(const float* __restrict__ Wout) {
    int idx = blockIdx.x * blockDim.x + threadIdx.x;    // 131072
    int r    = idx & 1;
    int lane = (idx >> 1) & 31;
    int nf   = (idx >> 6) & 15;
    int ks   = (idx >> 10) & 63;
    int tile = idx >> 16;
    int o = tile * 128 + nf * 8 + (lane >> 2);
    int k = ks * 8 + r * 4 + (lane & 3);
    float x = __ldg(Wout + (size_t)o * HID + k);
    uint32_t h = __float_as_uint(x) & 0xFFFFE000u;
    g_WOhi[idx] = h;
    g_WOlo[idx] = __float_as_uint(x - __uint_as_float(h));
}

// ================= xg_mma (3xTF32): g_xg = W_ih·x + bsum ====================
// grid (32, 64), 256 thr (8 warps). Tile 64 g x 64 b, K=256. A resident in
// SMEM; B fragments loaded DIRECTLY from fragment-permuted gmem (no staging,
// no per-timestep syncs — warps stream independently).
__global__ void __launch_bounds__(256, 1)
xg_mma()
{
    extern __shared__ uint32_t su[];
    uint32_t* sAhi = su;                 // 16384
    uint32_t* sAlo = su + 16384;
    uint32_t sbase = (uint32_t)__cvta_generic_to_shared(su);

    const int tid  = threadIdx.x;
    const int lane = tid & 31;
    const int w    = tid >> 5;
    const int wm   = w & 1, wn = w >> 1;     // wn 0..3 (2 nf each)
    const int group = lane >> 2, tg = lane & 3;
    const int tile = blockIdx.x;
    const int t0 = blockIdx.y * 8;

    // stage A (hi+lo) once
    {
        const uint32_t* srcH = g_Whi + (size_t)tile * 16384;
        const uint32_t* srcL = g_Wlo + (size_t)tile * 16384;
        #pragma unroll
        for (int it = 0; it < 16; it++) {
            int f4 = it * 256 + tid;
            cpa16(sbase + f4 * 16, srcH + f4 * 4);
            cpa16(sbase + 65536 + f4 * 16, srcL + f4 * 4);
        }
        CP_COMMIT();
        CP_WAIT0();
    }
    __syncthreads();

    float bias0[2], bias8[2];
    #pragma unroll
    for (int mi = 0; mi < 2; mi++) {
        int row = tile * 64 + wm * 32 + mi * 16 + group;
        bias0[mi] = g_bsum[row];
        bias8[mi] = g_bsum[row + 8];
    }

    for (int tt = 0; tt < 8; tt++) {
        const int t = t0 + tt;
        const uint32_t* bH = g_Xhi + (size_t)t * 16384 + (wn * 2) * 64 + lane * 2;
        const uint32_t* bL = g_Xlo + (size_t)t * 16384 + (wn * 2) * 64 + lane * 2;

        float acc[2][2][4];
        #pragma unroll
        for (int mi = 0; mi < 2; mi++)
            #pragma unroll
            for (int ni = 0; ni < 2; ni++)
                #pragma unroll
                for (int e = 0; e < 4; e++) acc[mi][ni][e] = 0.f;

        #pragma unroll 4
        for (int ks = 0; ks < 32; ks++) {
            uint32_t ahi[2][4], alo[2][4], bhi[2][2], blo[2][2];
            const int aoff = (ks * 4 + wm * 2) * 128 + lane * 4;
            #pragma unroll
            for (int mi = 0; mi < 2; mi++) {
                uint4 vh = *(const uint4*)(sAhi + aoff + mi * 128);
                ahi[mi][0] = vh.x; ahi[mi][1] = vh.y; ahi[mi][2] = vh.z; ahi[mi][3] = vh.w;
                uint4 vl = *(const uint4*)(sAlo + aoff + mi * 128);
                alo[mi][0] = vl.x; alo[mi][1] = vl.y; alo[mi][2] = vl.z; alo[mi][3] = vl.w;
            }
            #pragma unroll
            for (int ni = 0; ni < 2; ni++) {
                uint2 vh = __ldg((const uint2*)(bH + ks * 512 + ni * 64));
                bhi[ni][0] = vh.x; bhi[ni][1] = vh.y;
                uint2 vl = __ldg((const uint2*)(bL + ks * 512 + ni * 64));
                blo[ni][0] = vl.x; blo[ni][1] = vl.y;
            }
            #pragma unroll
            for (int mi = 0; mi < 2; mi++)
                #pragma unroll
                for (int ni = 0; ni < 2; ni++) {
                    mma8(acc[mi][ni], ahi[mi], bhi[ni]);
                    mma8(acc[mi][ni], alo[mi], bhi[ni]);
                    mma8(acc[mi][ni], ahi[mi], blo[ni]);
                }
        }

        #pragma unroll
        for (int mi = 0; mi < 2; mi++) {
            int row0 = tile * 64 + wm * 32 + mi * 16 + group;
            #pragma unroll
            for (int ni = 0; ni < 2; ni++) {
                int col = wn * 16 + ni * 8 + tg * 2;
                float* p0 = g_xg + ((size_t)t * G4 + row0) * BATCH + col;
                *(float2*)p0 = make_float2(acc[mi][ni][0] + bias0[mi],
                                           acc[mi][ni][1] + bias0[mi]);
                float* p1 = p0 + (size_t)8 * BATCH;
                *(float2*)p1 = make_float2(acc[mi][ni][2] + bias8[mi],
                                           acc[mi][ni][3] + bias8[mi]);
            }
        }
    }
}

// ================= out_mma (3xTF32): out[t][b][o] = h·W_out^T + b_out ======
// grid (2, 64), 128 thr. Tile 64 b x 128 o, K=512 staged in quarters.
// Layout placement validated by R9 run; split now mask-based (correct lo).
__global__ void __launch_bounds__(128, 1)
out_mma(const float* __restrict__ bout, float* __restrict__ out)
{
    extern __shared__ uint32_t su[];
    uint32_t* sBhi = su;                 // 16384
    uint32_t* sBlo = su + 16384;
    uint32_t* sAhi = su + 32768;         // 8192
    uint32_t* sAlo = su + 40960;
    uint32_t sbase = (uint32_t)__cvta_generic_to_shared(su);

    const int tid  = threadIdx.x;
    const int lane = tid & 31;
    const int w    = tid >> 5;
    const int wm   = w & 1, wn = w >> 1;
    const int group = lane >> 2, tg = lane & 3;
    const int tile = blockIdx.x;
    const int t0 = blockIdx.y * 8;

    float bo2[8][2];
    #pragma unroll
    for (int ni = 0; ni < 8; ni++) {
        int col = tile * 128 + wn * 64 + ni * 8 + tg * 2;
        bo2[ni][0] = bout[col];
        bo2[ni][1] = bout[col + 1];
    }

    for (int tt = 0; tt < 8; tt++) {
        const int t = t0 + tt;
        float acc[2][8][4];
        #pragma unroll
        for (int mi = 0; mi < 2; mi++)
            #pragma unroll
            for (int ni = 0; ni < 8; ni++)
                #pragma unroll
                for (int e = 0; e < 4; e++) acc[mi][ni][e] = 0.f;

        #pragma unroll
        for (int q = 0; q < 4; q++) {
            __syncthreads();
            const uint32_t* bH = g_WOhi + (size_t)tile * 65536 + q * 16384;
            const uint32_t* bL = g_WOlo + (size_t)tile * 65536 + q * 16384;
            #pragma unroll
            for (int it = 0; it < 32; it++) {
                int f4 = it * 128 + tid;
                cpa16(sbase + f4 * 16, bH + f4 * 4);
                cpa16(sbase + 65536 + f4 * 16, bL + f4 * 4);
            }
            const uint32_t* aH = g_Hhi + (size_t)t * 32768 + q * 8192;
            const uint32_t* aL = g_Hlo + (size_t)t * 32768 + q * 8192;
            #pragma unroll
            for (int it = 0; it < 16; it++) {
                int f4 = it * 128 + tid;
                cpa16(sbase + 131072 + f4 * 16, aH + f4 * 4);
                cpa16(sbase + 163840 + f4 * 16, aL + f4 * 4);
            }
            CP_COMMIT();
            CP_WAIT0();
            __syncthreads();

            #pragma unroll 2
            for (int ks = 0; ks < 16; ks++) {
                uint32_t ahi[2][4], alo[2][4];
                const int aoff = (ks * 4 + wm * 2) * 128 + lane * 4;
                #pragma unroll
                for (int mi = 0; mi < 2; mi++) {
                    uint4 vh = *(const uint4*)(sAhi + aoff + mi * 128);
                    ahi[mi][0] = vh.x; ahi[mi][1] = vh.y; ahi[mi][2] = vh.z; ahi[mi][3] = vh.w;
                    uint4 vl = *(const uint4*)(sAlo + aoff + mi * 128);
                    alo[mi][0] = vl.x; alo[mi][1] = vl.y; alo[mi][2] = vl.z; alo[mi][3] = vl.w;
                }
                const int boff = (ks * 16 + wn * 8) * 64 + lane * 2;
                #pragma unroll
                for (int ni = 0; ni < 8; ni++) {
                    uint2 vh = *(const uint2*)(sBhi + boff + ni * 64);
                    uint2 vl = *(const uint2*)(sBlo + boff + ni * 64);
                    uint32_t bhi[2] = {vh.x, vh.y};
                    uint32_t blo[2] = {vl.x, vl.y};
                    #pragma unroll
                    for (int mi = 0; mi < 2; mi++) {
                        mma8(acc[mi][ni], ahi[mi], bhi);
                        mma8(acc[mi][ni], alo[mi], bhi);
                        mma8(acc[mi][ni], ahi[mi], blo);
                    }
                }
            }
        }

        #pragma unroll
        for (int mi = 0; mi < 2; mi++) {
            int r0 = wm * 32 + mi * 16 + group;
            #pragma unroll
            for (int ni = 0; ni < 8; ni++) {
                int col = tile * 128 + wn * 64 + ni * 8 + tg * 2;
                float* p0 = out + ((size_t)t * BATCH + r0) * OUT_DIM + col;
                *(float2*)p0 = make_float2(acc[mi][ni][0] + bo2[ni][0],
                                           acc[mi][ni][1] + bo2[ni][1]);
                float* p1 = p0 + (size_t)8 * OUT_DIM;
                *(float2*)p1 = make_float2(acc[mi][ni][2] + bo2[ni][0],
                                           acc[mi][ni][3] + bo2[ni][1]);
            }
        }
    }
}

// ================= persistent recurrent kernel (R12-proven + h split store) =
__device__ __forceinline__ void loadh8(ulonglong2* hb, const float* p) {
    #pragma unroll
    for (int i = 0; i < 8; i++)
        hb[i] = __ldg((const ulonglong2*)(p + (size_t)i * BATCH));
}
__device__ __forceinline__ void comp8x2(ull acc[4][2][2], const ulonglong2* hb,
                                        const float* wslice, int iip2, int kl) {
    #pragma unroll
    for (int q = 0; q < 4; q++) {
        #pragma unroll
        for (int c = 0; c < 2; c++) {
            const float* wr = wslice + (q * 4 + iip2 + c) * SW2_STRIDE + 2 * kl;
            ulonglong2 w0 = *(const ulonglong2*)(wr);
            ulonglong2 w1 = *(const ulonglong2*)(wr + 4);
            ulonglong2 w2 = *(const ulonglong2*)(wr + 8);
            ulonglong2 w3 = *(const ulonglong2*)(wr + 12);
            ffma2(acc[q][c][0], hb[0].x, w0.x); ffma2(acc[q][c][1], hb[0].y, w0.x);
            ffma2(acc[q][c][0], hb[1].x, w0.y); ffma2(acc[q][c][1], hb[1].y, w0.y);
            ffma2(acc[q][c][0], hb[2].x, w1.x); ffma2(acc[q][c][1], hb[2].y, w1.x);
            ffma2(acc[q][c][0], hb[3].x, w1.y); ffma2(acc[q][c][1], hb[3].y, w1.y);
            ffma2(acc[q][c][0], hb[4].x, w2.x); ffma2(acc[q][c][1], hb[4].y, w2.x);
            ffma2(acc[q][c][0], hb[5].x, w2.y); ffma2(acc[q][c][1], hb[5].y, w2.y);
            ffma2(acc[q][c][0], hb[6].x, w3.x); ffma2(acc[q][c][1], hb[6].y, w3.x);
            ffma2(acc[q][c][0], hb[7].x, w3.y); ffma2(acc[q][c][1], hb[7].y, w3.y);
        }
    }
}

__global__ void __launch_bounds__(256, 1)
lstm_recurrent(const float* __restrict__ W_hh, float* __restrict__ out)
{
    extern __shared__ float smem[];
    float* sW2  = smem;                 // 16 x 1032 (splatted W_hh rows)
    float* sRed = smem + SW2_FLOATS;    // 256 x 36

    const int tid = threadIdx.x;
    const int j0  = blockIdx.x << 2;
    const int hk   = tid >> 5;
    const int lane = tid & 31;
    const int iip  = lane >> 4;
    const int bg   = (lane & 15) << 2;
    const int jj  = tid >> 6;
    const int bo  = tid & 63;
    const int j_out = j0 + jj;
    const int erow = (jj >> 1) * 16 + (bo >> 2);
    const int eoff = (jj & 1) * 16 + (bo & 3) * 4;

    // h split-store index (A-frag layout, validated in R9 run)
    const size_t hidx_base =
        (((size_t)(j_out >> 3) * 4 + (bo >> 4)) << 7)
        + (((bo & 7) * 4 + (j_out & 3)) << 2)
        + (((bo >> 3) & 1) | (((j_out >> 2) & 1) << 1));

    #pragma unroll
    for (int u = 0; u < 8; u++) {
        int f4 = u * 256 + tid;
        int rr = f4 >> 7;
        int kk = (f4 & 127) << 2;
        int q = rr >> 2, iw = rr & 3;
        float4 v = *(const float4*)(W_hh + (size_t)(q * HID + j0 + iw) * HID + kk);
        float* d = sW2 + rr * SW2_STRIDE + 2 * kk;
        *(float4*)(d    ) = make_float4(v.x, v.x, v.y, v.y);
        *(float4*)(d + 4) = make_float4(v.z, v.z, v.w, v.w);
    }
    __syncthreads();

    float creg = 0.f;
    const float* wslice = sW2 + hk * 128;
    const int iip2 = iip * 2;

    for (int t = 0; t < T_STEPS; t++) {
        float xg[4];
        #pragma unroll
        for (int q = 0; q < 4; q++)
            xg[q] = __ldg(g_xg + ((size_t)t * G4 + q * HID + j_out) * BATCH + bo);

        ull acc[4][2][2];
        #pragma unroll
        for (int q = 0; q < 4; q++)
            #pragma unroll
            for (int c = 0; c < 2; c++) { acc[q][c][0] = 0ull; acc[q][c][1] = 0ull; }

        if (t > 0) {
            const float* hsrc = g_hs + ((size_t)(t - 1) * HID + hk * 64) * BATCH + bg;
            ulonglong2 hb0[8], hb1[8];
            loadh8(hb0, hsrc);
            #pragma unroll
            for (int g2 = 0; g2 < 4; g2++) {
                loadh8(hb1, hsrc + (size_t)(2 * g2 + 1) * 8 * BATCH);
                comp8x2(acc, hb0, wslice, iip2, 2 * g2 * 8);
                loadh8(hb0, hsrc + (size_t)(2 * g2 + 2) * 8 * BATCH);
                comp8x2(acc, hb1, wslice, iip2, (2 * g2 + 1) * 8);
            }
        }

        {
            float* p = sRed + tid * SRED_STRIDE;
            #pragma unroll
            for (int c = 0; c < 2; c++) {
                float2 q0l = unpack2(acc[0][c][0]), q0h = unpack2(acc[0][c][1]);
                float2 q1l = unpack2(acc[1][c][0]), q1h = unpack2(acc[1][c][1]);
                float2 q2l = unpack2(acc[2][c][0]), q2h = unpack2(acc[2][c][1]);
                float2 q3l = unpack2(acc[3][c][0]), q3h = unpack2(acc[3][c][1]);
                *(float4*)(p + c * 16 + 0)  = make_float4(q0l.x, q1l.x, q2l.x, q3l.x);
                *(float4*)(p + c * 16 + 4)  = make_float4(q0l.y, q1l.y, q2l.y, q3l.y);
                *(float4*)(p + c * 16 + 8)  = make_float4(q0h.x, q1h.x, q2h.x, q3h.x);
                *(float4*)(p + c * 16 + 12) = make_float4(q0h.y, q1h.y, q2h.y, q3h.y);
            }
        }
        __syncthreads();

        {
            const float* rp = sRed + erow * SRED_STRIDE + eoff;
            float4 v0 = *(const float4*)(rp);
            float4 v1 = *(const float4*)(rp + 32 * SRED_STRIDE);
            float4 v2 = *(const float4*)(rp + 64 * SRED_STRIDE);
            float4 v3 = *(const float4*)(rp + 96 * SRED_STRIDE);
            float4 v4 = *(const float4*)(rp + 128 * SRED_STRIDE);
            float4 v5 = *(const float4*)(rp + 160 * SRED_STRIDE);
            float4 v6 = *(const float4*)(rp + 192 * SRED_STRIDE);
            float4 v7 = *(const float4*)(rp + 224 * SRED_STRIDE);
            float a0 = ((v0.x + v1.x) + (v2.x + v3.x)) + ((v4.x + v5.x) + (v6.x + v7.x)) + xg[0];
            float a1 = ((v0.y + v1.y) + (v2.y + v3.y)) + ((v4.y + v5.y) + (v6.y + v7.y)) + xg[1];
            float a2 = ((v0.z + v1.z) + (v2.z + v3.z)) + ((v4.z + v5.z) + (v6.z + v7.z)) + xg[2];
            float a3 = ((v0.w + v1.w) + (v2.w + v3.w)) + ((v4.w + v5.w) + (v6.w + v7.w)) + xg[3];
            float iv = sigf(a0);
            float fv = sigf(a1);
            float gv = tanhfast(a2);
            float ov = sigf(a3);
            creg = fv * creg + iv * gv;
            float hn = ov * tanhfast(creg);
            g_hs[((size_t)t * HID + j_out) * BATCH + bo] = hn;
            // mask-split h into A-frag layout for out_mma
            uint32_t hh = __float_as_uint(hn) & 0xFFFFE000u;
            size_t hidx = (size_t)t * 32768 + hidx_base;
            g_Hhi[hidx] = hh;
            g_Hlo[hidx] = __float_as_uint(hn - __uint_as_float(hh));
            if (t == T_STEPS - 1) {
                out[OFF_H + (size_t)bo * HID + j_out] = hn;
                out[OFF_C + (size_t)bo * HID + j_out] = creg;
            }
        }
        __syncthreads();

        if (tid == 0) {
            unsigned target = (unsigned)(t + 1) * NCTA;
            unsigned ret;
            asm volatile("atom.release.gpu.global.add.u32 %0, [%1], %2;"
                         : "=r"(ret) : "l"(&g_bar), "r"(1u) : "memory");
            if (ret == target - 1) {
                asm volatile("st.release.gpu.global.u32 [%0], %1;"
                             :: "l"(&g_flag), "r"((unsigned)(t + 1)) : "memory");
            } else {
                unsigned v;
                do {
                    asm volatile("ld.acquire.gpu.global.u32 %0, [%1];"
                                 : "=r"(v) : "l"(&g_flag) : "memory");
                } while (v < (unsigned)(t + 1));
            }
        }
        __syncthreads();
    }
}

// ---------------- launch ----------------
extern "C" void kernel_launch(void* const* d_in, const int* in_sizes, int n_in,
                              void* d_out, int out_size) {
    const float* inputs = (const float*)d_in[0];
    const float* W_ih   = (const float*)d_in[1];
    const float* W_hh   = (const float*)d_in[2];
    const float* b_ih   = (const float*)d_in[3];
    const float* b_hh   = (const float*)d_in[4];
    const float* W_out  = (const float*)d_in[5];
    const float* b_out  = (const float*)d_in[6];
    float* out = (float*)d_out;

    static int attr_done = 0;
    if (!attr_done) {
        cudaFuncSetAttribute(xg_mma,
                             cudaFuncAttributeMaxDynamicSharedMemorySize, XG_SMEM);
        cudaFuncSetAttribute(out_mma,
                             cudaFuncAttributeMaxDynamicSharedMemorySize, GO_SMEM);
        cudaFuncSetAttribute(lstm_recurrent,
                             cudaFuncAttributeMaxDynamicSharedMemorySize, RSMEM_BYTES);
        attr_done = 1;
    }

    reset_kernel<<<16, 256>>>(b_ih, b_hh);
    prep_W <<<2048, 256>>>(W_ih);
    prep_X <<<32768, 256>>>(inputs);
    prep_WO<<<512, 256>>>(W_out);

    xg_mma<<<dim3(32, 64), 256, XG_SMEM>>>();

    lstm_recurrent<<<NCTA, 256, RSMEM_BYTES>>>(W_hh, out);

    out_mma<<<dim3(2, 64), 128, GO_SMEM>>>(b_out, out);
}

// round 16
// speedup vs baseline: 1.0528x; 1.0528x over previous
#include <cuda_runtime.h>
#include <cstdint>

#define T_STEPS 512
#define BATCH   64
#define IN_DIM  256
#define HID     512
#define OUT_DIM 256
#define G4      2048
#define NCTA    128

#define SW2_STRIDE  1032
#define SW2_FLOATS  (16 * SW2_STRIDE)      // 16512
#define SRED_STRIDE 36
#define SRED_FLOATS (256 * SRED_STRIDE)    // 9216
#define RSMEM_BYTES ((SW2_FLOATS + SRED_FLOATS) * 4)   // 102912

#define XG_SMEM  196608   // A hi+lo 128KB + B 2 bufs x (16KB hi + 16KB lo)

#define OFF_H ((size_t)T_STEPS * BATCH * OUT_DIM)
#define OFF_C (OFF_H + (size_t)BATCH * HID)

typedef unsigned long long ull;

__device__ float    g_xg[(size_t)T_STEPS * G4 * BATCH];   // [t][g][b]
__device__ float    g_hs[(size_t)T_STEPS * HID * BATCH];  // [t][k][b]
__device__ float    g_bsum[G4];
__device__ unsigned g_bar;
__device__ unsigned g_flag;

// pre-split tf32 operands in fragment-permuted layouts (xgate only)
__device__ uint32_t g_Whi[32u * 16384u];        // [tile32][ks32][mf4][lane32][4]
__device__ uint32_t g_Wlo[32u * 16384u];
__device__ uint32_t g_Xhi[(size_t)T_STEPS * 16384u];   // [t][ks32][nf8][lane32][2]
__device__ uint32_t g_Xlo[(size_t)T_STEPS * 16384u];

// ---------------- helpers ----------------
__device__ __forceinline__ void ffma2(ull& d, ull a, ull b) {
    asm("fma.rn.f32x2 %0, %1, %2, %0;" : "+l"(d) : "l"(a), "l"(b));
}
__device__ __forceinline__ float2 unpack2(ull v) {
    float2 r; asm("mov.b64 {%0, %1}, %2;" : "=f"(r.x), "=f"(r.y) : "l"(v)); return r;
}
__device__ __forceinline__ float sigf(float x) {
    return __fdividef(1.f, 1.f + __expf(-x));
}
__device__ __forceinline__ float tanhfast(float x) {
    float e = __expf(-2.f * fabsf(x));
    float r = __fdividef(1.f - e, 1.f + e);
    return copysignf(r, x);
}
__device__ __forceinline__ void mma8(float* d, const uint32_t* a, const uint32_t* b) {
    asm volatile(
        "mma.sync.aligned.m16n8k8.row.col.f32.tf32.tf32.f32 "
        "{%0,%1,%2,%3}, {%4,%5,%6,%7}, {%8,%9}, {%0,%1,%2,%3};"
        : "+f"(d[0]), "+f"(d[1]), "+f"(d[2]), "+f"(d[3])
        : "r"(a[0]), "r"(a[1]), "r"(a[2]), "r"(a[3]), "r"(b[0]), "r"(b[1]));
}
__device__ __forceinline__ void cpa16(uint32_t d, const void* s) {
    asm volatile("cp.async.cg.shared.global [%0], [%1], 16;" :: "r"(d), "l"(s) : "memory");
}
#define CP_COMMIT()  asm volatile("cp.async.commit_group;" ::: "memory")
#define CP_WAIT0()   asm volatile("cp.async.wait_group 0;" ::: "memory")
#define CP_WAIT1()   asm volatile("cp.async.wait_group 1;" ::: "memory")

__global__ void reset_kernel(const float* __restrict__ b_ih,
                             const float* __restrict__ b_hh) {
    int idx = blockIdx.x * blockDim.x + threadIdx.x;
    if (idx == 0) { g_bar = 0u; g_flag = 0u; }
    if (idx < G4) g_bsum[idx] = b_ih[idx] + b_hh[idx];
}

// ---------------- prep_all: W_ih and inputs split+permute in ONE kernel -----
// (merged so lstm_recurrent is the 4th launch -> ncu captures it)
__global__ void prep_all(const float* __restrict__ W,
                         const float* __restrict__ inp) {
    int bx = blockIdx.x;
    int tid = threadIdx.x;
    if (bx < 2048) {
        int idx = bx * 256 + tid;                       // 524288
        int r    = idx & 3;
        int lane = (idx >> 2) & 31;
        int mf   = (idx >> 7) & 3;
        int ks   = (idx >> 9) & 31;
        int tile = idx >> 14;
        int m = tile * 64 + mf * 16 + (r & 1) * 8 + (lane >> 2);
        int k = ks * 8 + ((r >> 1) & 1) * 4 + (lane & 3);
        float x = __ldg(W + (size_t)m * IN_DIM + k);
        uint32_t h = __float_as_uint(x) & 0xFFFFE000u;
        g_Whi[idx] = h;
        g_Wlo[idx] = __float_as_uint(x - __uint_as_float(h));
    } else {
        int idx = (bx - 2048) * 256 + tid;              // 8388608
        int r    = idx & 1;
        int lane = (idx >> 1) & 31;
        int nf   = (idx >> 6) & 7;
        int ks   = (idx >> 9) & 31;
        int t    = idx >> 14;
        int b = nf * 8 + (lane >> 2);
        int k = ks * 8 + r * 4 + (lane & 3);
        float x = __ldg(inp + ((size_t)t * BATCH + b) * IN_DIM + k);
        uint32_t h = __float_as_uint(x) & 0xFFFFE000u;
        g_Xhi[idx] = h;
        g_Xlo[idx] = __float_as_uint(x - __uint_as_float(h));
    }
}

// ================= xg_mma (3xTF32): g_xg = W_ih·x + bsum ====================
// grid (32, 64), 256 thr (8 warps). Tile 64 g x 64 b, K=256. A resident.
// B staged in QUARTERS (8 ks = 32KB hi+lo), 2-buffer cp.async ring so loads
// overlap MMA compute (R14's half staging serialized on wait).
__global__ void __launch_bounds__(256, 1)
xg_mma()
{
    extern __shared__ uint32_t su[];
    uint32_t* sAhi = su;                 // 16384
    uint32_t* sAlo = su + 16384;
    uint32_t* sB   = su + 32768;         // 2 bufs x (4096 hi + 4096 lo)
    uint32_t sbase = (uint32_t)__cvta_generic_to_shared(su);
    const uint32_t sbB = sbase + 131072;

    const int tid  = threadIdx.x;
    const int lane = tid & 31;
    const int w    = tid >> 5;
    const int wm   = w & 1, wn = w >> 1;     // wn 0..3 (2 nf each)
    const int group = lane >> 2, tg = lane & 3;
    const int tile = blockIdx.x;
    const int t0 = blockIdx.y * 8;

    // stage A (hi+lo) once; completion folded into first quarter wait
    {
        const uint32_t* srcH = g_Whi + (size_t)tile * 16384;
        const uint32_t* srcL = g_Wlo + (size_t)tile * 16384;
        #pragma unroll
        for (int it = 0; it < 16; it++) {
            int f4 = it * 256 + tid;
            cpa16(sbase + f4 * 16, srcH + f4 * 4);
            cpa16(sbase + 65536 + f4 * 16, srcL + f4 * 4);
        }
        CP_COMMIT();
    }

    float bias0[2], bias8[2];
    #pragma unroll
    for (int mi = 0; mi < 2; mi++) {
        int row = tile * 64 + wm * 32 + mi * 16 + group;
        bias0[mi] = g_bsum[row];
        bias8[mi] = g_bsum[row + 8];
    }

    for (int tt = 0; tt < 8; tt++) {
        const int t = t0 + tt;
        const uint32_t* bHt = g_Xhi + (size_t)t * 16384;
        const uint32_t* bLt = g_Xlo + (size_t)t * 16384;

        // prologue: stage quarters 0,1 into bufs 0,1
        #pragma unroll
        for (int qq = 0; qq < 2; qq++) {
            #pragma unroll
            for (int it = 0; it < 4; it++) {
                int f4 = it * 256 + tid;
                cpa16(sbB + qq * 32768 + f4 * 16,        bHt + qq * 4096 + f4 * 4);
                cpa16(sbB + qq * 32768 + 16384 + f4 * 16, bLt + qq * 4096 + f4 * 4);
            }
            CP_COMMIT();
        }

        float acc[2][2][4];
        #pragma unroll
        for (int mi = 0; mi < 2; mi++)
            #pragma unroll
            for (int ni = 0; ni < 2; ni++)
                #pragma unroll
                for (int e = 0; e < 4; e++) acc[mi][ni][e] = 0.f;

        #pragma unroll
        for (int q = 0; q < 4; q++) {
            if (q < 3) { CP_WAIT1(); } else { CP_WAIT0(); }
            __syncthreads();

            const uint32_t* bbuf = sB + (q & 1) * 8192;
            #pragma unroll
            for (int ksl = 0; ksl < 8; ksl++) {
                const int gks = q * 8 + ksl;
                uint32_t ahi[2][4], alo[2][4], bhi[2][2], blo[2][2];
                const int aoff = (gks * 4 + wm * 2) * 128 + lane * 4;
                #pragma unroll
                for (int mi = 0; mi < 2; mi++) {
                    uint4 vh = *(const uint4*)(sAhi + aoff + mi * 128);
                    ahi[mi][0] = vh.x; ahi[mi][1] = vh.y; ahi[mi][2] = vh.z; ahi[mi][3] = vh.w;
                    uint4 vl = *(const uint4*)(sAlo + aoff + mi * 128);
                    alo[mi][0] = vl.x; alo[mi][1] = vl.y; alo[mi][2] = vl.z; alo[mi][3] = vl.w;
                }
                const uint32_t* bb = bbuf + ksl * 512 + (wn * 2) * 64 + lane * 2;
                #pragma unroll
                for (int ni = 0; ni < 2; ni++) {
                    uint2 vh = *(const uint2*)(bb + ni * 64);
                    bhi[ni][0] = vh.x; bhi[ni][1] = vh.y;
                    uint2 vl = *(const uint2*)(bb + 4096 + ni * 64);
                    blo[ni][0] = vl.x; blo[ni][1] = vl.y;
                }
                #pragma unroll
                for (int mi = 0; mi < 2; mi++)
                    #pragma unroll
                    for (int ni = 0; ni < 2; ni++) {
                        mma8(acc[mi][ni], ahi[mi], bhi[ni]);
                        mma8(acc[mi][ni], alo[mi], bhi[ni]);
                        mma8(acc[mi][ni], ahi[mi], blo[ni]);
                    }
            }
            __syncthreads();   // all warps done reading buf (q&1)

            if (q < 2) {       // stage quarter q+2 into the buffer just freed
                const int qq = q + 2;
                #pragma unroll
                for (int it = 0; it < 4; it++) {
                    int f4 = it * 256 + tid;
                    cpa16(sbB + (q & 1) * 32768 + f4 * 16,
                          bHt + qq * 4096 + f4 * 4);
                    cpa16(sbB + (q & 1) * 32768 + 16384 + f4 * 16,
                          bLt + qq * 4096 + f4 * 4);
                }
                CP_COMMIT();
            }
        }

        #pragma unroll
        for (int mi = 0; mi < 2; mi++) {
            int row0 = tile * 64 + wm * 32 + mi * 16 + group;
            #pragma unroll
            for (int ni = 0; ni < 2; ni++) {
                int col = wn * 16 + ni * 8 + tg * 2;
                float* p0 = g_xg + ((size_t)t * G4 + row0) * BATCH + col;
                *(float2*)p0 = make_float2(acc[mi][ni][0] + bias0[mi],
                                           acc[mi][ni][1] + bias0[mi]);
                float* p1 = p0 + (size_t)8 * BATCH;
                *(float2*)p1 = make_float2(acc[mi][ni][2] + bias8[mi],
                                           acc[mi][ni][3] + bias8[mi]);
            }
        }
    }
}

// ================= gemm_out (R5-proven): out[t][b][o] = h·W_out^T + b_out ===
__global__ __launch_bounds__(256) void gemm_out(
    const float* __restrict__ Wout, const float* __restrict__ bout,
    float* __restrict__ out)
{
    __shared__ float As2[16][68];
    __shared__ float Wsw[16 * 196];
    const int t  = blockIdx.y;
    const int n0 = blockIdx.x * 64;
    const int tid = threadIdx.x;
    const int tx = tid & 15, ty = tid >> 4;
    const float* A = g_hs + (size_t)t * HID * BATCH;

    ull acc[2][4];
    #pragma unroll
    for (int i = 0; i < 2; i++)
        #pragma unroll
        for (int n = 0; n < 4; n++) acc[i][n] = 0ull;

    const int rr = tid >> 2;
    const int kq = (tid & 3) << 2;
    const int obase = (rr >> 2) * 12 + (rr & 3) * 2;
    const int akk = tid >> 4, ac4 = (tid & 15) * 4;

    for (int k0 = 0; k0 < HID; k0 += 16) {
        *(float4*)&As2[akk][ac4] = *(const float4*)(A + (size_t)(k0 + akk) * BATCH + ac4);
        {
            float4 v = *(const float4*)(Wout + (size_t)(n0 + rr) * HID + k0 + kq);
            *(float2*)&Wsw[(kq + 0) * 196 + obase] = make_float2(v.x, v.x);
            *(float2*)&Wsw[(kq + 1) * 196 + obase] = make_float2(v.y, v.y);
            *(float2*)&Wsw[(kq + 2) * 196 + obase] = make_float2(v.z, v.z);
            *(float2*)&Wsw[(kq + 3) * 196 + obase] = make_float2(v.w, v.w);
        }
        __syncthreads();
        #pragma unroll
        for (int kk = 0; kk < 16; kk++) {
            ulonglong2 a = *(const ulonglong2*)&As2[kk][ty * 4];
            const float* wp = Wsw + kk * 196 + tx * 12;
            ulonglong2 w01 = *(const ulonglong2*)wp;
            ulonglong2 w23 = *(const ulonglong2*)(wp + 4);
            ffma2(acc[0][0], a.x, w01.x); ffma2(acc[1][0], a.y, w01.x);
            ffma2(acc[0][1], a.x, w01.y); ffma2(acc[1][1], a.y, w01.y);
            ffma2(acc[0][2], a.x, w23.x); ffma2(acc[1][2], a.y, w23.x);
            ffma2(acc[0][3], a.x, w23.y); ffma2(acc[1][3], a.y, w23.y);
        }
        __syncthreads();
    }

    float4 bb = *(const float4*)(bout + n0 + tx * 4);
    float2 u[2][4];
    #pragma unroll
    for (int p = 0; p < 2; p++)
        #pragma unroll
        for (int n = 0; n < 4; n++) u[p][n] = unpack2(acc[p][n]);
    #pragma unroll
    for (int bi = 0; bi < 4; bi++) {
        int p = bi >> 1;
        float4 r;
        if (bi & 1) r = make_float4(u[p][0].y + bb.x, u[p][1].y + bb.y,
                                    u[p][2].y + bb.z, u[p][3].y + bb.w);
        else        r = make_float4(u[p][0].x + bb.x, u[p][1].x + bb.y,
                                    u[p][2].x + bb.z, u[p][3].x + bb.w);
        *(float4*)(out + ((size_t)t * BATCH + ty * 4 + bi) * OUT_DIM + n0 + tx * 4) = r;
    }
}

// ================= persistent recurrent kernel (R12-proven, unchanged) ======
__device__ __forceinline__ void loadh8(ulonglong2* hb, const float* p) {
    #pragma unroll
    for (int i = 0; i < 8; i++)
        hb[i] = __ldg((const ulonglong2*)(p + (size_t)i * BATCH));
}
__device__ __forceinline__ void comp8x2(ull acc[4][2][2], const ulonglong2* hb,
                                        const float* wslice, int iip2, int kl) {
    #pragma unroll
    for (int q = 0; q < 4; q++) {
        #pragma unroll
        for (int c = 0; c < 2; c++) {
            const float* wr = wslice + (q * 4 + iip2 + c) * SW2_STRIDE + 2 * kl;
            ulonglong2 w0 = *(const ulonglong2*)(wr);
            ulonglong2 w1 = *(const ulonglong2*)(wr + 4);
            ulonglong2 w2 = *(const ulonglong2*)(wr + 8);
            ulonglong2 w3 = *(const ulonglong2*)(wr + 12);
            ffma2(acc[q][c][0], hb[0].x, w0.x); ffma2(acc[q][c][1], hb[0].y, w0.x);
            ffma2(acc[q][c][0], hb[1].x, w0.y); ffma2(acc[q][c][1], hb[1].y, w0.y);
            ffma2(acc[q][c][0], hb[2].x, w1.x); ffma2(acc[q][c][1], hb[2].y, w1.x);
            ffma2(acc[q][c][0], hb[3].x, w1.y); ffma2(acc[q][c][1], hb[3].y, w1.y);
            ffma2(acc[q][c][0], hb[4].x, w2.x); ffma2(acc[q][c][1], hb[4].y, w2.x);
            ffma2(acc[q][c][0], hb[5].x, w2.y); ffma2(acc[q][c][1], hb[5].y, w2.y);
            ffma2(acc[q][c][0], hb[6].x, w3.x); ffma2(acc[q][c][1], hb[6].y, w3.x);
            ffma2(acc[q][c][0], hb[7].x, w3.y); ffma2(acc[q][c][1], hb[7].y, w3.y);
        }
    }
}

__global__ void __launch_bounds__(256, 1)
lstm_recurrent(const float* __restrict__ W_hh, float* __restrict__ out)
{
    extern __shared__ float smem[];
    float* sW2  = smem;                 // 16 x 1032 (splatted W_hh rows)
    float* sRed = smem + SW2_FLOATS;    // 256 x 36

    const int tid = threadIdx.x;
    const int j0  = blockIdx.x << 2;
    const int hk   = tid >> 5;
    const int lane = tid & 31;
    const int iip  = lane >> 4;
    const int bg   = (lane & 15) << 2;
    const int jj  = tid >> 6;
    const int bo  = tid & 63;
    const int j_out = j0 + jj;
    const int erow = (jj >> 1) * 16 + (bo >> 2);
    const int eoff = (jj & 1) * 16 + (bo & 3) * 4;

    #pragma unroll
    for (int u = 0; u < 8; u++) {
        int f4 = u * 256 + tid;
        int rr = f4 >> 7;
        int kk = (f4 & 127) << 2;
        int q = rr >> 2, iw = rr & 3;
        float4 v = *(const float4*)(W_hh + (size_t)(q * HID + j0 + iw) * HID + kk);
        float* d = sW2 + rr * SW2_STRIDE + 2 * kk;
        *(float4*)(d    ) = make_float4(v.x, v.x, v.y, v.y);
        *(float4*)(d + 4) = make_float4(v.z, v.z, v.w, v.w);
    }
    __syncthreads();

    float creg = 0.f;
    const float* wslice = sW2 + hk * 128;
    const int iip2 = iip * 2;

    for (int t = 0; t < T_STEPS; t++) {
        float xg[4];
        #pragma unroll
        for (int q = 0; q < 4; q++)
            xg[q] = __ldg(g_xg + ((size_t)t * G4 + q * HID + j_out) * BATCH + bo);

        ull acc[4][2][2];
        #pragma unroll
        for (int q = 0; q < 4; q++)
            #pragma unroll
            for (int c = 0; c < 2; c++) { acc[q][c][0] = 0ull; acc[q][c][1] = 0ull; }

        if (t > 0) {
            const float* hsrc = g_hs + ((size_t)(t - 1) * HID + hk * 64) * BATCH + bg;
            ulonglong2 hb0[8], hb1[8];
            loadh8(hb0, hsrc);
            #pragma unroll
            for (int g2 = 0; g2 < 4; g2++) {
                loadh8(hb1, hsrc + (size_t)(2 * g2 + 1) * 8 * BATCH);
                comp8x2(acc, hb0, wslice, iip2, 2 * g2 * 8);
                loadh8(hb0, hsrc + (size_t)(2 * g2 + 2) * 8 * BATCH);
                comp8x2(acc, hb1, wslice, iip2, (2 * g2 + 1) * 8);
            }
        }

        {
            float* p = sRed + tid * SRED_STRIDE;
            #pragma unroll
            for (int c = 0; c < 2; c++) {
                float2 q0l = unpack2(acc[0][c][0]), q0h = unpack2(acc[0][c][1]);
                float2 q1l = unpack2(acc[1][c][0]), q1h = unpack2(acc[1][c][1]);
                float2 q2l = unpack2(acc[2][c][0]), q2h = unpack2(acc[2][c][1]);
                float2 q3l = unpack2(acc[3][c][0]), q3h = unpack2(acc[3][c][1]);
                *(float4*)(p + c * 16 + 0)  = make_float4(q0l.x, q1l.x, q2l.x, q3l.x);
                *(float4*)(p + c * 16 + 4)  = make_float4(q0l.y, q1l.y, q2l.y, q3l.y);
                *(float4*)(p + c * 16 + 8)  = make_float4(q0h.x, q1h.x, q2h.x, q3h.x);
                *(float4*)(p + c * 16 + 12) = make_float4(q0h.y, q1h.y, q2h.y, q3h.y);
            }
        }
        __syncthreads();

        {
            const float* rp = sRed + erow * SRED_STRIDE + eoff;
            float4 v0 = *(const float4*)(rp);
            float4 v1 = *(const float4*)(rp + 32 * SRED_STRIDE);
            float4 v2 = *(const float4*)(rp + 64 * SRED_STRIDE);
            float4 v3 = *(const float4*)(rp + 96 * SRED_STRIDE);
            float4 v4 = *(const float4*)(rp + 128 * SRED_STRIDE);
            float4 v5 = *(const float4*)(rp + 160 * SRED_STRIDE);
            float4 v6 = *(const float4*)(rp + 192 * SRED_STRIDE);
            float4 v7 = *(const float4*)(rp + 224 * SRED_STRIDE);
            float a0 = ((v0.x + v1.x) + (v2.x + v3.x)) + ((v4.x + v5.x) + (v6.x + v7.x)) + xg[0];
            float a1 = ((v0.y + v1.y) + (v2.y + v3.y)) + ((v4.y + v5.y) + (v6.y + v7.y)) + xg[1];
            float a2 = ((v0.z + v1.z) + (v2.z + v3.z)) + ((v4.z + v5.z) + (v6.z + v7.z)) + xg[2];
            float a3 = ((v0.w + v1.w) + (v2.w + v3.w)) + ((v4.w + v5.w) + (v6.w + v7.w)) + xg[3];
            float iv = sigf(a0);
            float fv = sigf(a1);
            float gv = tanhfast(a2);
            float ov = sigf(a3);
            creg = fv * creg + iv * gv;
            float hn = ov * tanhfast(creg);
            g_hs[((size_t)t * HID + j_out) * BATCH + bo] = hn;
            if (t == T_STEPS - 1) {
                out[OFF_H + (size_t)bo * HID + j_out] = hn;
                out[OFF_C + (size_t)bo * HID + j_out] = creg;
            }
        }
        __syncthreads();

        if (tid == 0) {
            unsigned target = (unsigned)(t + 1) * NCTA;
            unsigned ret;
            asm volatile("atom.release.gpu.global.add.u32 %0, [%1], %2;"
                         : "=r"(ret) : "l"(&g_bar), "r"(1u) : "memory");
            if (ret == target - 1) {
                asm volatile("st.release.gpu.global.u32 [%0], %1;"
                             :: "l"(&g_flag), "r"((unsigned)(t + 1)) : "memory");
            } else {
                unsigned v;
                do {
                    asm volatile("ld.acquire.gpu.global.u32 %0, [%1];"
                                 : "=r"(v) : "l"(&g_flag) : "memory");
                } while (v < (unsigned)(t + 1));
            }
        }
        __syncthreads();
    }
}

// ---------------- launch ----------------
extern "C" void kernel_launch(void* const* d_in, const int* in_sizes, int n_in,
                              void* d_out, int out_size) {
    const float* inputs = (const float*)d_in[0];
    const float* W_ih   = (const float*)d_in[1];
    const float* W_hh   = (const float*)d_in[2];
    const float* b_ih   = (const float*)d_in[3];
    const float* b_hh   = (const float*)d_in[4];
    const float* W_out  = (const float*)d_in[5];
    const float* b_out  = (const float*)d_in[6];
    float* out = (float*)d_out;

    static int attr_done = 0;
    if (!attr_done) {
        cudaFuncSetAttribute(xg_mma,
                             cudaFuncAttributeMaxDynamicSharedMemorySize, XG_SMEM);
        cudaFuncSetAttribute(lstm_recurrent,
                             cudaFuncAttributeMaxDynamicSharedMemorySize, RSMEM_BYTES);
        attr_done = 1;
    }

    reset_kernel<<<16, 256>>>(b_ih, b_hh);          // launch 1
    prep_all<<<34816, 256>>>(W_ih, inputs);         // launch 2

    xg_mma<<<dim3(32, 64), 256, XG_SMEM>>>();       // launch 3

    lstm_recurrent<<<NCTA, 256, RSMEM_BYTES>>>(W_hh, out);   // launch 4 (ncu)

    gemm_out<<<dim3(OUT_DIM / 64, T_STEPS), 256>>>(W_out, b_out, out);  // 5
}